// round 13
// baseline (speedup 1.0000x reference)
#include <cuda_runtime.h>
#include <math.h>
#include <stdint.h>

// ---------------------------------------------------------------------------
// QuantSoftmax: B=32, C=128, H=W=80 (HW=6400). int32 input (int8 repr, zp=0),
// float32 output. Piecewise-quantized exp (qint16) + reciprocal (qint16),
// requantized to int8*OUT_SCALE.
//
// exp collapses to a 256-entry LUT over d = qmax-q; each CTA builds it in
// smem (expf). Single kernel. Structure: 64 pixels/CTA, 128 threads,
// 2 threads/pixel (warp = 32 consecutive pixels -> full 128B coalescing).
// This revision: q bytes live in REGISTERS (no staging buffer at all);
// LUT replicated 16x (float, 16KB) -> ~2-wavefront lookups; pass 3 redoes
// the lookup instead of reading cached exp. Float channel-sums are exact
// (integer-valued, < 2^22). 18.4KB smem, 11+ CTAs/SM.
// ---------------------------------------------------------------------------

#define C_DIM 128
#define HW_DIM 6400
#define PX 64          // pixels per block
#define NTHREADS 128   // 2 threads per pixel
#define KITER 16       // 64 channels / 4 per u32

__device__ __forceinline__ float quant_i16(float y, float scale) {
    float q = rintf(__fdiv_rn(y, scale));           // jnp.round = half-even
    return fminf(fmaxf(q, -32768.0f), 32767.0f);
}

// build one exp-LUT entry: d = qmax - q in [0,255], x = -d*ds
__device__ __forceinline__ float exp_lut_entry(int i, float ds) {
    const float ESCALE = (float)(2.0 / 65535.0);
    float x = __fmul_rn(-(float)i, ds);
    float y = quant_i16(expf(-40.0f), ESCALE);      // left constant
    if (x >= -40.0f) {                              // line (-40,-20)
        float y0 = expf(-40.0f), y1 = expf(-20.0f);
        float t = __fadd_rn(y0, __fmul_rn(__fadd_rn(x, 40.0f),
                                          __fdiv_rn(__fadd_rn(y1, -y0), 20.0f)));
        y = quant_i16(t, ESCALE);
    }
    if (x >= -20.0f) {                              // table (-20,-10)
        float idxf = rintf(__fmul_rn(__fadd_rn(x, 20.0f), (float)(255.0 / 10.0)));
        idxf = fminf(fmaxf(idxf, 0.0f), 255.0f);
        float step = __fdiv_rn(10.0f, 255.0f);
        float xs = __fadd_rn(-20.0f, __fmul_rn(idxf, step));
        y = quant_i16(expf(xs), ESCALE);
    }
    if (x >= -10.0f) {                              // table (-10,0)
        float idxf = rintf(__fmul_rn(__fadd_rn(x, 10.0f), (float)(255.0 / 10.0)));
        idxf = fminf(fmaxf(idxf, 0.0f), 255.0f);
        float step = __fdiv_rn(10.0f, 255.0f);
        float xs = __fadd_rn(-10.0f, __fmul_rn(idxf, step));
        y = quant_i16(expf(xs), ESCALE);
    }
    if (x >= 0.0f) {                                // line (0,1): only d=0
        float y0 = expf(0.0f), y1 = expf(1.0f);
        float t = __fadd_rn(y0, __fmul_rn(x, __fdiv_rn(__fadd_rn(y1, -y0), 1.0f)));
        y = quant_i16(t, ESCALE);
    }
    if (x > 1.0f) y = quant_i16(expf(1.0f), ESCALE);
    return y;
}

__global__ __launch_bounds__(NTHREADS, 11)
void quant_softmax_kernel(const int* __restrict__ in, float* __restrict__ out,
                          const float* __restrict__ ds_ptr) {
    __shared__ float slut[256 * 16];   // 16x replicated: slut[d*16 + (tid&15)]
    __shared__ float scratch[256];     // un-replicated LUT (build staging)
    __shared__ int   smax[NTHREADS];
    __shared__ float ssum[NTHREADS];

    int tid = threadIdx.x;
    int h = tid >> 6;                  // half: channels [h*64, h*64+64)
    int px = tid & 63;                 // pixel within tile
    int rp = tid & 15;                 // LUT replica slot

    int tile = blockIdx.x;             // b * 100 + t
    int b = tile / (HW_DIM / PX);
    int hw = (tile % (HW_DIM / PX)) * PX + px;

    const int* p = in + (size_t)b * C_DIM * HW_DIM + (size_t)(h * 64) * HW_DIM + hw;

    // ---- pass 1: load own 64 channels into 16 byte-packed regs, max ----
    unsigned w[16];
    unsigned mx4 = 0x80808080u;        // all lanes = -128
#pragma unroll
    for (int k = 0; k < KITER; k++) {
        int q0 = __ldcs(&p[(4 * k + 0) * HW_DIM]);
        int q1 = __ldcs(&p[(4 * k + 1) * HW_DIM]);
        int q2 = __ldcs(&p[(4 * k + 2) * HW_DIM]);
        int q3 = __ldcs(&p[(4 * k + 3) * HW_DIM]);
        unsigned t01 = __byte_perm((unsigned)q0, (unsigned)q1, 0x0040);
        unsigned t23 = __byte_perm((unsigned)q2, (unsigned)q3, 0x0040);
        unsigned t = __byte_perm(t01, t23, 0x5410);   // [q0,q1,q2,q3] low bytes
        mx4 = __vmaxs4(mx4, t);
        w[k] = t;
    }
    int mp = (int)(signed char)(mx4 & 0xFF);
    mp = max(mp, (int)(signed char)((mx4 >> 8) & 0xFF));
    mp = max(mp, (int)(signed char)((mx4 >> 16) & 0xFF));
    mp = max(mp, (int)(signed char)(mx4 >> 24));
    smax[tid] = mp;

    // ---- build un-replicated LUT (2 entries/thread) ----
    float ds = __ldg(ds_ptr);
    scratch[tid] = exp_lut_entry(tid, ds);
    scratch[tid + 128] = exp_lut_entry(tid + 128, ds);
    __syncthreads();                   // scratch + smax ready

    // cross-half max (safe to read smax after barrier)
    int m = max(smax[px], smax[px + 64]);
    unsigned m4 = (unsigned)(m & 0xFF) * 0x01010101u;

    // ---- replicate LUT 16x (broadcast reads, conflict-free writes) ----
#pragma unroll
    for (int i = 0; i < 32; i++) {
        int j = tid + i * NTHREADS;    // 0..4095
        slut[j] = scratch[j >> 4];
    }
    __syncthreads();                   // slut ready

    // ---- pass 2: d via VSUB4, replicated LUT, exact float sum ----
    float sum = 0.0f;
#pragma unroll
    for (int k = 0; k < KITER; k++) {
        unsigned d4 = __vsub4(m4, w[k]);      // per-byte (m-q) mod 256 = d
        w[k] = d4;                            // keep d for pass 3
        int a0 = (int)__byte_perm(d4, 0, 0x4440);
        int a1 = (int)__byte_perm(d4, 0, 0x4441);
        int a2 = (int)__byte_perm(d4, 0, 0x4442);
        int a3 = (int)__byte_perm(d4, 0, 0x4443);
        float e0 = slut[a0 * 16 + rp];
        float e1 = slut[a1 * 16 + rp];
        float e2 = slut[a2 * 16 + rp];
        float e3 = slut[a3 * 16 + rp];
        sum += (e0 + e1) + (e2 + e3);         // integer-valued < 2^22: exact
    }
    ssum[tid] = sum;
    __syncthreads();
    sum = ssum[px] + ssum[px + 64];           // exact

    // ---- reciprocal (both half-threads compute identically) ----
    // shift = ceil(log2(128)) = 7
    float sum_sh = rintf(sum * 0.0078125f);                 // exact /128
    sum_sh = fminf(fmaxf(sum_sh, -32768.0f), 32767.0f);
    const float DIVSC = (float)(2.0 / 65535.0 * 128.0);
    float v = __fmul_rn(sum_sh, DIVSC);
    const float RSCALE = (float)((1.0 / 0.1) * 2.0 / 65535.0);

    float r = quant_i16(__fdiv_rn(1.0f, 0.001f), RSCALE);   // left const
    if (v >= 0.001f) {                                      // line (0.001,0.1)
        float y0 = __fdiv_rn(1.0f, 0.001f), y1 = __fdiv_rn(1.0f, 0.1f);
        float t = __fadd_rn(y0, __fmul_rn(__fadd_rn(v, -0.001f),
                                          __fdiv_rn(__fadd_rn(y1, -y0), (float)(0.1 - 0.001))));
        r = quant_i16(t, RSCALE);
    }
    if (v >= 0.1f) {                                        // table (0.1,250): compute entry
        float idxf = rintf(__fmul_rn(__fadd_rn(v, -0.1f), (float)(255.0 / 249.9)));
        idxf = fminf(fmaxf(idxf, 0.0f), 255.0f);
        float step1 = __fdiv_rn((float)(250.0 - 0.1), 255.0f);
        float xs = __fadd_rn(0.1f, __fmul_rn(idxf, step1));
        r = quant_i16(__fdiv_rn(1.0f, xs), RSCALE);
    }
    if (v >= 250.0f) {                                      // table (250,500): compute entry
        float idxf = rintf(__fmul_rn(__fadd_rn(v, -250.0f), (float)(255.0 / 250.0)));
        idxf = fminf(fmaxf(idxf, 0.0f), 255.0f);
        float step2 = __fdiv_rn(250.0f, 255.0f);
        float xs = __fadd_rn(250.0f, __fmul_rn(idxf, step2));
        r = quant_i16(__fdiv_rn(1.0f, xs), RSCALE);
    }
    if (v >= 500.0f) {                                      // line (500,700)
        float y0 = __fdiv_rn(1.0f, 500.0f), y1 = __fdiv_rn(1.0f, 700.0f);
        float t = __fadd_rn(y0, __fmul_rn(__fadd_rn(v, -500.0f),
                                          __fdiv_rn(__fadd_rn(y1, -y0), 200.0f)));
        r = quant_i16(t, RSCALE);
    }
    if (v > 700.0f) r = quant_i16(__fdiv_rn(1.0f, 700.0f), RSCALE);

    // ---- pass 3: re-lookup exp, out = clip(round((e*r)*K), i8)*OUT_SCALE ----
    const float KF = (float)((2.0 / 65535.0) * ((1.0 / 0.1) * 2.0 / 65535.0) / (2.0 / 255.0));
    const float OUTSC = (float)(2.0 / 255.0);
    float* po = out + (size_t)b * C_DIM * HW_DIM + (size_t)(h * 64) * HW_DIM + hw;
#pragma unroll
    for (int k = 0; k < KITER; k++) {
        unsigned d4 = w[k];
        int a0 = (int)__byte_perm(d4, 0, 0x4440);
        int a1 = (int)__byte_perm(d4, 0, 0x4441);
        int a2 = (int)__byte_perm(d4, 0, 0x4442);
        int a3 = (int)__byte_perm(d4, 0, 0x4443);
        float e0 = slut[a0 * 16 + rp];
        float e1 = slut[a1 * 16 + rp];
        float e2 = slut[a2 * 16 + rp];
        float e3 = slut[a3 * 16 + rp];
        float p0 = rintf(__fmul_rn(__fmul_rn(e0, r), KF));
        float p1 = rintf(__fmul_rn(__fmul_rn(e1, r), KF));
        float p2 = rintf(__fmul_rn(__fmul_rn(e2, r), KF));
        float p3 = rintf(__fmul_rn(__fmul_rn(e3, r), KF));
        p0 = fminf(fmaxf(p0, -128.0f), 127.0f);
        p1 = fminf(fmaxf(p1, -128.0f), 127.0f);
        p2 = fminf(fmaxf(p2, -128.0f), 127.0f);
        p3 = fminf(fmaxf(p3, -128.0f), 127.0f);
        __stcs(&po[(4 * k + 0) * HW_DIM], p0 * OUTSC);
        __stcs(&po[(4 * k + 1) * HW_DIM], p1 * OUTSC);
        __stcs(&po[(4 * k + 2) * HW_DIM], p2 * OUTSC);
        __stcs(&po[(4 * k + 3) * HW_DIM], p3 * OUTSC);
    }
}

extern "C" void kernel_launch(void* const* d_in, const int* in_sizes, int n_in,
                              void* d_out, int out_size) {
    const int* data = (const int*)d_in[0];
    const float* data_scale = (const float*)d_in[1];
    float* out = (float*)d_out;

    int total = in_sizes[0];
    int B = total / (C_DIM * HW_DIM);
    int blocks = B * (HW_DIM / PX);
    quant_softmax_kernel<<<blocks, NTHREADS>>>(data, out, data_scale);
}

// round 15
// speedup vs baseline: 1.2950x; 1.2950x over previous
#include <cuda_runtime.h>
#include <math.h>
#include <stdint.h>

// ---------------------------------------------------------------------------
// QuantSoftmax: B=32, C=128, H=W=80 (HW=6400). int32 input (int8 repr, zp=0),
// float32 output. Piecewise-quantized exp (qint16) + reciprocal (qint16),
// requantized to int8*OUT_SCALE.
//
// exp collapses to a 256-entry LUT over d = qmax-q; each CTA builds it in
// smem (expf) once. Single kernel, single wave: 1600 CTAs x 2 tiles each
// (< 148*12 concurrent). Tile = 64 pixels, 128 threads.
// Pass 1: thread = pixel-pair x 32 channels, int2 loads (LDG.64) + STS.64
// into the 16KB staging buffer (byte-packed q, 4ch/u32).
// Pass 2/3 (R11-proven): thread = pixel x 64 channels; d via VSUB4, integer
// LUT lookups + integer channel sum (exact < 2^22), exp_q repacked in place,
// per-pixel piecewise reciprocal computed arithmetically.
// ---------------------------------------------------------------------------

#define C_DIM 128
#define HW_DIM 6400
#define PX 64          // pixels per tile
#define NTHREADS 128
#define KITER 16       // pass 2/3: 64 channels / 4 per u32
#define NBLOCKS 1600
#define TILES_PER_CTA 2

__device__ __forceinline__ float quant_i16(float y, float scale) {
    float q = rintf(__fdiv_rn(y, scale));           // jnp.round = half-even
    return fminf(fmaxf(q, -32768.0f), 32767.0f);
}

// build one exp-LUT entry: d = qmax - q in [0,255], x = -d*ds
__device__ __forceinline__ float exp_lut_entry(int i, float ds) {
    const float ESCALE = (float)(2.0 / 65535.0);
    float x = __fmul_rn(-(float)i, ds);
    float y = quant_i16(expf(-40.0f), ESCALE);      // left constant
    if (x >= -40.0f) {                              // line (-40,-20)
        float y0 = expf(-40.0f), y1 = expf(-20.0f);
        float t = __fadd_rn(y0, __fmul_rn(__fadd_rn(x, 40.0f),
                                          __fdiv_rn(__fadd_rn(y1, -y0), 20.0f)));
        y = quant_i16(t, ESCALE);
    }
    if (x >= -20.0f) {                              // table (-20,-10)
        float idxf = rintf(__fmul_rn(__fadd_rn(x, 20.0f), (float)(255.0 / 10.0)));
        idxf = fminf(fmaxf(idxf, 0.0f), 255.0f);
        float step = __fdiv_rn(10.0f, 255.0f);
        float xs = __fadd_rn(-20.0f, __fmul_rn(idxf, step));
        y = quant_i16(expf(xs), ESCALE);
    }
    if (x >= -10.0f) {                              // table (-10,0)
        float idxf = rintf(__fmul_rn(__fadd_rn(x, 10.0f), (float)(255.0 / 10.0)));
        idxf = fminf(fmaxf(idxf, 0.0f), 255.0f);
        float step = __fdiv_rn(10.0f, 255.0f);
        float xs = __fadd_rn(-10.0f, __fmul_rn(idxf, step));
        y = quant_i16(expf(xs), ESCALE);
    }
    if (x >= 0.0f) {                                // line (0,1): only d=0
        float y0 = expf(0.0f), y1 = expf(1.0f);
        float t = __fadd_rn(y0, __fmul_rn(x, __fdiv_rn(__fadd_rn(y1, -y0), 1.0f)));
        y = quant_i16(t, ESCALE);
    }
    if (x > 1.0f) y = quant_i16(expf(1.0f), ESCALE);
    return y;
}

__global__ __launch_bounds__(NTHREADS, 12)
void quant_softmax_kernel(const int* __restrict__ in, float* __restrict__ out,
                          const float* __restrict__ ds_ptr) {
    // In-place union buffer, 16 KB:
    //   pass 1: even slots 2G (G = global 4-ch group 0..31) <- byte-packed q
    //   pass 2: slots 2G / 2G+1 <- u16x2 exp_q
    __shared__ uint32_t buf[64 * PX];
    __shared__ unsigned slut_i[256];   // exp_q as u32 integer
    __shared__ int smax[256];          // per (channel-slice, pixel) max
    __shared__ int ssum[NTHREADS];

    int tid = threadIdx.x;

    // ---- build LUT once per CTA ----
    float ds = __ldg(ds_ptr);
    slut_i[tid] = (unsigned)(int)exp_lut_entry(tid, ds);
    slut_i[tid + 128] = (unsigned)(int)exp_lut_entry(tid + 128, ds);

    // pass-1 mapping: pixel-pair p, channel-slice cs (32 channels)
    int p1_p = tid & 31;
    int p1_cs = tid >> 5;
    // pass-2/3 mapping: pixel px, channel-half h (64 channels)
    int h = tid >> 6;
    int px = tid & 63;

    const float DIVSC = (float)(2.0 / 65535.0 * 128.0);
    const float RSCALE = (float)((1.0 / 0.1) * 2.0 / 65535.0);
    const float KF = (float)((2.0 / 65535.0) * ((1.0 / 0.1) * 2.0 / 65535.0) / (2.0 / 255.0));
    const float OUTSC = (float)(2.0 / 255.0);

#pragma unroll
    for (int t = 0; t < TILES_PER_CTA; t++) {
        int tile = blockIdx.x * TILES_PER_CTA + t;    // 0..3199
        int b = tile / (HW_DIM / PX);
        int tilehw = (tile % (HW_DIM / PX)) * PX;

        __syncthreads();   // t=0: LUT ready; t>0: buf/smax/ssum free for reuse

        // ---- pass 1: int2 loads, byte-pack both pixels, STS.64 ----
        {
            int hw2 = tilehw + 2 * p1_p;
            const int* p = in + (size_t)b * C_DIM * HW_DIM
                              + (size_t)(p1_cs * 32) * HW_DIM + hw2;
            unsigned mxa = 0x80808080u, mxb = 0x80808080u;
#pragma unroll
            for (int g = 0; g < 8; g++) {
                int2 v0 = __ldcs((const int2*)&p[(4 * g + 0) * HW_DIM]);
                int2 v1 = __ldcs((const int2*)&p[(4 * g + 1) * HW_DIM]);
                int2 v2 = __ldcs((const int2*)&p[(4 * g + 2) * HW_DIM]);
                int2 v3 = __ldcs((const int2*)&p[(4 * g + 3) * HW_DIM]);
                unsigned ta = __byte_perm(__byte_perm((unsigned)v0.x, (unsigned)v1.x, 0x0040),
                                          __byte_perm((unsigned)v2.x, (unsigned)v3.x, 0x0040),
                                          0x5410);
                unsigned tb = __byte_perm(__byte_perm((unsigned)v0.y, (unsigned)v1.y, 0x0040),
                                          __byte_perm((unsigned)v2.y, (unsigned)v3.y, 0x0040),
                                          0x5410);
                mxa = __vmaxs4(mxa, ta);
                mxb = __vmaxs4(mxb, tb);
                int slot = 2 * (p1_cs * 8 + g);       // even slot
                *(uint2*)&buf[slot * PX + 2 * p1_p] = make_uint2(ta, tb);
            }
            int ma = (int)(signed char)(mxa & 0xFF);
            ma = max(ma, (int)(signed char)((mxa >> 8) & 0xFF));
            ma = max(ma, (int)(signed char)((mxa >> 16) & 0xFF));
            ma = max(ma, (int)(signed char)(mxa >> 24));
            int mb = (int)(signed char)(mxb & 0xFF);
            mb = max(mb, (int)(signed char)((mxb >> 8) & 0xFF));
            mb = max(mb, (int)(signed char)((mxb >> 16) & 0xFF));
            mb = max(mb, (int)(signed char)(mxb >> 24));
            *(int2*)&smax[p1_cs * 64 + 2 * p1_p] = make_int2(ma, mb);
        }
        __syncthreads();

        // ---- cross-slice max for this pixel ----
        int m = max(max(smax[px], smax[64 + px]), max(smax[128 + px], smax[192 + px]));
        unsigned m4 = (unsigned)(m & 0xFF) * 0x01010101u;   // broadcast max byte

        // ---- pass 2: d via VSUB4, integer LUT, integer sum; pack exp_q ----
        int sa = 0, sb = 0;
#pragma unroll
        for (int k = 0; k < KITER; k++) {
            unsigned w = buf[(h * 32 + 2 * k) * PX + px];
            unsigned d4 = __vsub4(m4, w);             // per-byte (m-q) mod 256 = d
            int a0 = (int)__byte_perm(d4, 0, 0x4440);
            int a1 = (int)__byte_perm(d4, 0, 0x4441);
            int a2 = (int)__byte_perm(d4, 0, 0x4442);
            int a3 = (int)__byte_perm(d4, 0, 0x4443);
            unsigned e0 = slut_i[a0];
            unsigned e1 = slut_i[a1];
            unsigned e2 = slut_i[a2];
            unsigned e3 = slut_i[a3];
            sa += (int)(e0 + e1);
            sb += (int)(e2 + e3);                     // total < 2^22: exact
            buf[(h * 32 + 2 * k + 0) * PX + px] = __byte_perm(e0, e1, 0x5410);
            buf[(h * 32 + 2 * k + 1) * PX + px] = __byte_perm(e2, e3, 0x5410);
        }
        ssum[tid] = sa + sb;
        __syncthreads();
        float sum = (float)(ssum[px] + ssum[px + 64]);  // exact I2F (< 2^22)

        // ---- reciprocal (both half-threads compute identically) ----
        // shift = ceil(log2(128)) = 7
        float sum_sh = rintf(sum * 0.0078125f);                 // exact /128
        sum_sh = fminf(fmaxf(sum_sh, -32768.0f), 32767.0f);
        float v = __fmul_rn(sum_sh, DIVSC);

        float r = quant_i16(__fdiv_rn(1.0f, 0.001f), RSCALE);   // left const
        if (v >= 0.001f) {                                      // line (0.001,0.1)
            float y0 = __fdiv_rn(1.0f, 0.001f), y1 = __fdiv_rn(1.0f, 0.1f);
            float tt = __fadd_rn(y0, __fmul_rn(__fadd_rn(v, -0.001f),
                                               __fdiv_rn(__fadd_rn(y1, -y0), (float)(0.1 - 0.001))));
            r = quant_i16(tt, RSCALE);
        }
        if (v >= 0.1f) {                                        // table (0.1,250)
            float idxf = rintf(__fmul_rn(__fadd_rn(v, -0.1f), (float)(255.0 / 249.9)));
            idxf = fminf(fmaxf(idxf, 0.0f), 255.0f);
            float step1 = __fdiv_rn((float)(250.0 - 0.1), 255.0f);
            float xs = __fadd_rn(0.1f, __fmul_rn(idxf, step1));
            r = quant_i16(__fdiv_rn(1.0f, xs), RSCALE);
        }
        if (v >= 250.0f) {                                      // table (250,500)
            float idxf = rintf(__fmul_rn(__fadd_rn(v, -250.0f), (float)(255.0 / 250.0)));
            idxf = fminf(fmaxf(idxf, 0.0f), 255.0f);
            float step2 = __fdiv_rn(250.0f, 255.0f);
            float xs = __fadd_rn(250.0f, __fmul_rn(idxf, step2));
            r = quant_i16(__fdiv_rn(1.0f, xs), RSCALE);
        }
        if (v >= 500.0f) {                                      // line (500,700)
            float y0 = __fdiv_rn(1.0f, 500.0f), y1 = __fdiv_rn(1.0f, 700.0f);
            float tt = __fadd_rn(y0, __fmul_rn(__fadd_rn(v, -500.0f),
                                               __fdiv_rn(__fadd_rn(y1, -y0), 200.0f)));
            r = quant_i16(tt, RSCALE);
        }
        if (v > 700.0f) r = quant_i16(__fdiv_rn(1.0f, 700.0f), RSCALE);

        // ---- pass 3: out = clip(round((exp_q*recip_q)*K), i8) * OUT_SCALE ----
        float* po = out + (size_t)b * C_DIM * HW_DIM
                        + (size_t)(h * 64) * HW_DIM + tilehw + px;
#pragma unroll
        for (int k = 0; k < KITER; k++) {
            unsigned w0 = buf[(h * 32 + 2 * k + 0) * PX + px];
            unsigned w1 = buf[(h * 32 + 2 * k + 1) * PX + px];
            float e0 = (float)(int)__byte_perm(w0, 0, 0x4410);  // w0 & 0xFFFF
            float e1 = (float)(w0 >> 16);
            float e2 = (float)(int)__byte_perm(w1, 0, 0x4410);
            float e3 = (float)(w1 >> 16);
            float p0 = rintf(__fmul_rn(__fmul_rn(e0, r), KF));
            float p1 = rintf(__fmul_rn(__fmul_rn(e1, r), KF));
            float p2 = rintf(__fmul_rn(__fmul_rn(e2, r), KF));
            float p3 = rintf(__fmul_rn(__fmul_rn(e3, r), KF));
            p0 = fminf(fmaxf(p0, -128.0f), 127.0f);
            p1 = fminf(fmaxf(p1, -128.0f), 127.0f);
            p2 = fminf(fmaxf(p2, -128.0f), 127.0f);
            p3 = fminf(fmaxf(p3, -128.0f), 127.0f);
            __stcs(&po[(4 * k + 0) * HW_DIM], p0 * OUTSC);
            __stcs(&po[(4 * k + 1) * HW_DIM], p1 * OUTSC);
            __stcs(&po[(4 * k + 2) * HW_DIM], p2 * OUTSC);
            __stcs(&po[(4 * k + 3) * HW_DIM], p3 * OUTSC);
        }
    }
}

extern "C" void kernel_launch(void* const* d_in, const int* in_sizes, int n_in,
                              void* d_out, int out_size) {
    const int* data = (const int*)d_in[0];
    const float* data_scale = (const float*)d_in[1];
    float* out = (float*)d_out;

    quant_softmax_kernel<<<NBLOCKS, NTHREADS>>>(data, out, data_scale);
}

// round 16
// speedup vs baseline: 1.4152x; 1.0928x over previous
#include <cuda_runtime.h>
#include <math.h>
#include <stdint.h>

// ---------------------------------------------------------------------------
// QuantSoftmax: B=32, C=128, H=W=80 (HW=6400). int32 input (int8 repr, zp=0),
// float32 output. Piecewise-quantized exp (qint16) + reciprocal (qint16),
// requantized to int8*OUT_SCALE.
//
// exp collapses to a 256-entry LUT over d = qmax-q; each CTA builds it in
// smem (expf). Single kernel, grid 3200 (R11-proven shape: 64 px/CTA,
// 128 threads, 12 CTAs/SM).
// Pass 1: thread = pixel-pair x 32-channel slice, int2 loads (LDG.64) +
// STS.64 into the 16KB staging buffer (byte-packed q, 4ch/u32). Slot layout
// identical to R11's.
// Pass 2/3 (R11 verbatim): thread = pixel x 64 channels; d via VSUB4,
// integer LUT + integer channel sum (exact < 2^22), exp_q repacked in place,
// per-pixel piecewise reciprocal computed arithmetically.
// ---------------------------------------------------------------------------

#define C_DIM 128
#define HW_DIM 6400
#define PX 64          // pixels per block
#define NTHREADS 128
#define KITER 16       // pass 2/3: 64 channels / 4 per u32

__device__ __forceinline__ float quant_i16(float y, float scale) {
    float q = rintf(__fdiv_rn(y, scale));           // jnp.round = half-even
    return fminf(fmaxf(q, -32768.0f), 32767.0f);
}

// build one exp-LUT entry: d = qmax - q in [0,255], x = -d*ds
__device__ __forceinline__ float exp_lut_entry(int i, float ds) {
    const float ESCALE = (float)(2.0 / 65535.0);
    float x = __fmul_rn(-(float)i, ds);
    float y = quant_i16(expf(-40.0f), ESCALE);      // left constant
    if (x >= -40.0f) {                              // line (-40,-20)
        float y0 = expf(-40.0f), y1 = expf(-20.0f);
        float t = __fadd_rn(y0, __fmul_rn(__fadd_rn(x, 40.0f),
                                          __fdiv_rn(__fadd_rn(y1, -y0), 20.0f)));
        y = quant_i16(t, ESCALE);
    }
    if (x >= -20.0f) {                              // table (-20,-10)
        float idxf = rintf(__fmul_rn(__fadd_rn(x, 20.0f), (float)(255.0 / 10.0)));
        idxf = fminf(fmaxf(idxf, 0.0f), 255.0f);
        float step = __fdiv_rn(10.0f, 255.0f);
        float xs = __fadd_rn(-20.0f, __fmul_rn(idxf, step));
        y = quant_i16(expf(xs), ESCALE);
    }
    if (x >= -10.0f) {                              // table (-10,0)
        float idxf = rintf(__fmul_rn(__fadd_rn(x, 10.0f), (float)(255.0 / 10.0)));
        idxf = fminf(fmaxf(idxf, 0.0f), 255.0f);
        float step = __fdiv_rn(10.0f, 255.0f);
        float xs = __fadd_rn(-10.0f, __fmul_rn(idxf, step));
        y = quant_i16(expf(xs), ESCALE);
    }
    if (x >= 0.0f) {                                // line (0,1): only d=0
        float y0 = expf(0.0f), y1 = expf(1.0f);
        float t = __fadd_rn(y0, __fmul_rn(x, __fdiv_rn(__fadd_rn(y1, -y0), 1.0f)));
        y = quant_i16(t, ESCALE);
    }
    if (x > 1.0f) y = quant_i16(expf(1.0f), ESCALE);
    return y;
}

__global__ __launch_bounds__(NTHREADS, 12)
void quant_softmax_kernel(const int* __restrict__ in, float* __restrict__ out,
                          const float* __restrict__ ds_ptr) {
    // In-place union buffer, 16 KB:
    //   pass 1: even slot 2*(cs*8+g) holds byte-packed q (4 ch) per pixel
    //   pass 2: slots 2k / 2k+1 (per h) <- u16x2 exp_q
    __shared__ uint32_t buf[64 * PX];
    __shared__ unsigned slut_i[256];   // exp_q as u32 integer
    __shared__ int smax[256];          // [cs*64 + px] per-slice pixel max
    __shared__ int ssum[NTHREADS];

    int tid = threadIdx.x;
    // pass-1 mapping: pixel-pair p1_p, channel-slice p1_cs (32 channels)
    int p1_p = tid & 31;
    int p1_cs = tid >> 5;
    // pass-2/3 mapping: pixel px, channel-half h (64 channels)
    int h = tid >> 6;
    int px = tid & 63;

    int tile = blockIdx.x;             // b * 100 + t
    int b = tile / (HW_DIM / PX);
    int tilehw = (tile % (HW_DIM / PX)) * PX;

    // ---- pass 1 FIRST (loads in flight while LUT is built below) ----
    {
        int hw2 = tilehw + 2 * p1_p;
        const int* p = in + (size_t)b * C_DIM * HW_DIM
                          + (size_t)(p1_cs * 32) * HW_DIM + hw2;
        unsigned mxa = 0x80808080u, mxb = 0x80808080u;
#pragma unroll
        for (int g = 0; g < 8; g++) {
            int2 v0 = __ldcs((const int2*)&p[(4 * g + 0) * HW_DIM]);
            int2 v1 = __ldcs((const int2*)&p[(4 * g + 1) * HW_DIM]);
            int2 v2 = __ldcs((const int2*)&p[(4 * g + 2) * HW_DIM]);
            int2 v3 = __ldcs((const int2*)&p[(4 * g + 3) * HW_DIM]);
            unsigned ta = __byte_perm(__byte_perm((unsigned)v0.x, (unsigned)v1.x, 0x0040),
                                      __byte_perm((unsigned)v2.x, (unsigned)v3.x, 0x0040),
                                      0x5410);
            unsigned tb = __byte_perm(__byte_perm((unsigned)v0.y, (unsigned)v1.y, 0x0040),
                                      __byte_perm((unsigned)v2.y, (unsigned)v3.y, 0x0040),
                                      0x5410);
            mxa = __vmaxs4(mxa, ta);
            mxb = __vmaxs4(mxb, tb);
            int slot = 2 * (p1_cs * 8 + g);       // even slot, same map as R11
            *(uint2*)&buf[slot * PX + 2 * p1_p] = make_uint2(ta, tb);
        }
        int ma = (int)(signed char)(mxa & 0xFF);
        ma = max(ma, (int)(signed char)((mxa >> 8) & 0xFF));
        ma = max(ma, (int)(signed char)((mxa >> 16) & 0xFF));
        ma = max(ma, (int)(signed char)(mxa >> 24));
        int mb = (int)(signed char)(mxb & 0xFF);
        mb = max(mb, (int)(signed char)((mxb >> 8) & 0xFF));
        mb = max(mb, (int)(signed char)((mxb >> 16) & 0xFF));
        mb = max(mb, (int)(signed char)(mxb >> 24));
        *(int2*)&smax[p1_cs * 64 + 2 * p1_p] = make_int2(ma, mb);
    }

    // ---- LUT build (overlaps outstanding loads of other warps) ----
    float ds = __ldg(ds_ptr);
    slut_i[tid] = (unsigned)(int)exp_lut_entry(tid, ds);
    slut_i[tid + 128] = (unsigned)(int)exp_lut_entry(tid + 128, ds);
    __syncthreads();                   // covers buf + smax + slut_i

    // ---- cross-slice max for this pixel ----
    int m = max(max(smax[px], smax[64 + px]), max(smax[128 + px], smax[192 + px]));
    unsigned m4 = (unsigned)(m & 0xFF) * 0x01010101u;   // broadcast max byte

    // ---- pass 2: d via VSUB4, integer LUT, integer sum; pack exp_q ----
    int sa = 0, sb = 0;
#pragma unroll
    for (int k = 0; k < KITER; k++) {
        unsigned w = buf[(h * 32 + 2 * k) * PX + px];
        unsigned d4 = __vsub4(m4, w);                   // per-byte (m-q) mod 256 = d
        int a0 = (int)__byte_perm(d4, 0, 0x4440);
        int a1 = (int)__byte_perm(d4, 0, 0x4441);
        int a2 = (int)__byte_perm(d4, 0, 0x4442);
        int a3 = (int)__byte_perm(d4, 0, 0x4443);
        unsigned e0 = slut_i[a0];
        unsigned e1 = slut_i[a1];
        unsigned e2 = slut_i[a2];
        unsigned e3 = slut_i[a3];
        sa += (int)(e0 + e1);
        sb += (int)(e2 + e3);                           // total < 2^22: exact
        buf[(h * 32 + 2 * k + 0) * PX + px] = __byte_perm(e0, e1, 0x5410);
        buf[(h * 32 + 2 * k + 1) * PX + px] = __byte_perm(e2, e3, 0x5410);
    }
    ssum[tid] = sa + sb;
    __syncthreads();
    float sum = (float)(ssum[px] + ssum[px + 64]);      // exact I2F (< 2^22)

    // ---- reciprocal (both half-threads compute identically) ----
    // shift = ceil(log2(128)) = 7
    float sum_sh = rintf(sum * 0.0078125f);                 // exact /128
    sum_sh = fminf(fmaxf(sum_sh, -32768.0f), 32767.0f);
    const float DIVSC = (float)(2.0 / 65535.0 * 128.0);
    float v = __fmul_rn(sum_sh, DIVSC);
    const float RSCALE = (float)((1.0 / 0.1) * 2.0 / 65535.0);

    float r = quant_i16(__fdiv_rn(1.0f, 0.001f), RSCALE);   // left const
    if (v >= 0.001f) {                                      // line (0.001,0.1)
        float y0 = __fdiv_rn(1.0f, 0.001f), y1 = __fdiv_rn(1.0f, 0.1f);
        float t = __fadd_rn(y0, __fmul_rn(__fadd_rn(v, -0.001f),
                                          __fdiv_rn(__fadd_rn(y1, -y0), (float)(0.1 - 0.001))));
        r = quant_i16(t, RSCALE);
    }
    if (v >= 0.1f) {                                        // table (0.1,250): compute entry
        float idxf = rintf(__fmul_rn(__fadd_rn(v, -0.1f), (float)(255.0 / 249.9)));
        idxf = fminf(fmaxf(idxf, 0.0f), 255.0f);
        float step1 = __fdiv_rn((float)(250.0 - 0.1), 255.0f);
        float xs = __fadd_rn(0.1f, __fmul_rn(idxf, step1));
        r = quant_i16(__fdiv_rn(1.0f, xs), RSCALE);
    }
    if (v >= 250.0f) {                                      // table (250,500): compute entry
        float idxf = rintf(__fmul_rn(__fadd_rn(v, -250.0f), (float)(255.0 / 250.0)));
        idxf = fminf(fmaxf(idxf, 0.0f), 255.0f);
        float step2 = __fdiv_rn(250.0f, 255.0f);
        float xs = __fadd_rn(250.0f, __fmul_rn(idxf, step2));
        r = quant_i16(__fdiv_rn(1.0f, xs), RSCALE);
    }
    if (v >= 500.0f) {                                      // line (500,700)
        float y0 = __fdiv_rn(1.0f, 500.0f), y1 = __fdiv_rn(1.0f, 700.0f);
        float t = __fadd_rn(y0, __fmul_rn(__fadd_rn(v, -500.0f),
                                          __fdiv_rn(__fadd_rn(y1, -y0), 200.0f)));
        r = quant_i16(t, RSCALE);
    }
    if (v > 700.0f) r = quant_i16(__fdiv_rn(1.0f, 700.0f), RSCALE);

    // ---- pass 3: out = clip(round((exp_q*recip_q)*K), i8) * OUT_SCALE ----
    const float KF = (float)((2.0 / 65535.0) * ((1.0 / 0.1) * 2.0 / 65535.0) / (2.0 / 255.0));
    const float OUTSC = (float)(2.0 / 255.0);
    float* po = out + (size_t)b * C_DIM * HW_DIM + (size_t)(h * 64) * HW_DIM + tilehw + px;
#pragma unroll
    for (int k = 0; k < KITER; k++) {
        unsigned w0 = buf[(h * 32 + 2 * k + 0) * PX + px];
        unsigned w1 = buf[(h * 32 + 2 * k + 1) * PX + px];
        float e0 = (float)(int)__byte_perm(w0, 0, 0x4410);  // w0 & 0xFFFF
        float e1 = (float)(w0 >> 16);
        float e2 = (float)(int)__byte_perm(w1, 0, 0x4410);
        float e3 = (float)(w1 >> 16);
        float p0 = rintf(__fmul_rn(__fmul_rn(e0, r), KF));
        float p1 = rintf(__fmul_rn(__fmul_rn(e1, r), KF));
        float p2 = rintf(__fmul_rn(__fmul_rn(e2, r), KF));
        float p3 = rintf(__fmul_rn(__fmul_rn(e3, r), KF));
        p0 = fminf(fmaxf(p0, -128.0f), 127.0f);
        p1 = fminf(fmaxf(p1, -128.0f), 127.0f);
        p2 = fminf(fmaxf(p2, -128.0f), 127.0f);
        p3 = fminf(fmaxf(p3, -128.0f), 127.0f);
        __stcs(&po[(4 * k + 0) * HW_DIM], p0 * OUTSC);
        __stcs(&po[(4 * k + 1) * HW_DIM], p1 * OUTSC);
        __stcs(&po[(4 * k + 2) * HW_DIM], p2 * OUTSC);
        __stcs(&po[(4 * k + 3) * HW_DIM], p3 * OUTSC);
    }
}

extern "C" void kernel_launch(void* const* d_in, const int* in_sizes, int n_in,
                              void* d_out, int out_size) {
    const int* data = (const int*)d_in[0];
    const float* data_scale = (const float*)d_in[1];
    float* out = (float*)d_out;

    int total = in_sizes[0];
    int B = total / (C_DIM * HW_DIM);
    int blocks = B * (HW_DIM / PX);
    quant_softmax_kernel<<<blocks, NTHREADS>>>(data, out, data_scale);
}

// round 17
// speedup vs baseline: 1.4373x; 1.0156x over previous
#include <cuda_runtime.h>
#include <math.h>
#include <stdint.h>

// ---------------------------------------------------------------------------
// QuantSoftmax: B=32, C=128, H=W=80 (HW=6400). int32 input (int8 repr, zp=0),
// float32 output. Piecewise-quantized exp (qint16) + reciprocal (qint16),
// requantized to int8*OUT_SCALE.
//
// exp collapses to a 256-entry LUT over d = qmax-q; each CTA builds it in
// smem (expf). Single kernel, grid 3200, 64 px/CTA, 128 threads.
// UNIFORM mapping for all passes: thread = pixel-PAIR (p=tid&31) x 32-channel
// slice (cs=tid>>5). Warp spans 64 consecutive pixels -> every LDG.64/STG.64
// is 256B coalesced. q lives in registers across one barrier (no q staging).
// exp_q staged u16-packed ACROSS the pixel pair: one u32 per channel (8KB).
// Reciprocal computed once per pixel by 64 threads (srec). Integer LUT +
// integer channel sums (exact < 2^22).
// ---------------------------------------------------------------------------

#define C_DIM 128
#define HW_DIM 6400
#define PX 64          // pixels per block
#define NTHREADS 128

__device__ __forceinline__ float quant_i16(float y, float scale) {
    float q = rintf(__fdiv_rn(y, scale));           // jnp.round = half-even
    return fminf(fmaxf(q, -32768.0f), 32767.0f);
}

// build one exp-LUT entry: d = qmax - q in [0,255], x = -d*ds
__device__ __forceinline__ float exp_lut_entry(int i, float ds) {
    const float ESCALE = (float)(2.0 / 65535.0);
    float x = __fmul_rn(-(float)i, ds);
    float y = quant_i16(expf(-40.0f), ESCALE);      // left constant
    if (x >= -40.0f) {                              // line (-40,-20)
        float y0 = expf(-40.0f), y1 = expf(-20.0f);
        float t = __fadd_rn(y0, __fmul_rn(__fadd_rn(x, 40.0f),
                                          __fdiv_rn(__fadd_rn(y1, -y0), 20.0f)));
        y = quant_i16(t, ESCALE);
    }
    if (x >= -20.0f) {                              // table (-20,-10)
        float idxf = rintf(__fmul_rn(__fadd_rn(x, 20.0f), (float)(255.0 / 10.0)));
        idxf = fminf(fmaxf(idxf, 0.0f), 255.0f);
        float step = __fdiv_rn(10.0f, 255.0f);
        float xs = __fadd_rn(-20.0f, __fmul_rn(idxf, step));
        y = quant_i16(expf(xs), ESCALE);
    }
    if (x >= -10.0f) {                              // table (-10,0)
        float idxf = rintf(__fmul_rn(__fadd_rn(x, 10.0f), (float)(255.0 / 10.0)));
        idxf = fminf(fmaxf(idxf, 0.0f), 255.0f);
        float step = __fdiv_rn(10.0f, 255.0f);
        float xs = __fadd_rn(-10.0f, __fmul_rn(idxf, step));
        y = quant_i16(expf(xs), ESCALE);
    }
    if (x >= 0.0f) {                                // line (0,1): only d=0
        float y0 = expf(0.0f), y1 = expf(1.0f);
        float t = __fadd_rn(y0, __fmul_rn(x, __fdiv_rn(__fadd_rn(y1, -y0), 1.0f)));
        y = quant_i16(t, ESCALE);
    }
    if (x > 1.0f) y = quant_i16(expf(1.0f), ESCALE);
    return y;
}

__global__ __launch_bounds__(NTHREADS, 10)
void quant_softmax_kernel(const int* __restrict__ in, float* __restrict__ out,
                          const float* __restrict__ ds_ptr) {
    __shared__ uint32_t buf16[C_DIM * 32];   // [channel][pair]: u16x2 exp (8 KB)
    __shared__ unsigned slut_i[256];         // exp_q as u32 integer
    __shared__ int smax[256];                // [cs*64 + px] per-slice pixel max
    __shared__ int ssum[256];                // [cs*64 + px] per-slice pixel sum
    __shared__ float srec[PX];               // per-pixel recip_q

    int tid = threadIdx.x;
    int p = tid & 31;                 // pixel pair: pixels 2p, 2p+1
    int cs = tid >> 5;                // 32-channel slice

    int tile = blockIdx.x;            // b * 100 + t
    int b = tile / (HW_DIM / PX);
    int tilehw = (tile % (HW_DIM / PX)) * PX;

    const int* pin = in + (size_t)b * C_DIM * HW_DIM
                        + (size_t)(cs * 32) * HW_DIM + tilehw + 2 * p;

    // ---- pass 1: int2 loads, byte-pack per pixel, q stays in registers ----
    unsigned qa[8], qb[8];
    unsigned mxa = 0x80808080u, mxb = 0x80808080u;
#pragma unroll
    for (int g = 0; g < 8; g++) {
        int2 v0 = __ldcs((const int2*)&pin[(4 * g + 0) * HW_DIM]);
        int2 v1 = __ldcs((const int2*)&pin[(4 * g + 1) * HW_DIM]);
        int2 v2 = __ldcs((const int2*)&pin[(4 * g + 2) * HW_DIM]);
        int2 v3 = __ldcs((const int2*)&pin[(4 * g + 3) * HW_DIM]);
        unsigned ta = __byte_perm(__byte_perm((unsigned)v0.x, (unsigned)v1.x, 0x0040),
                                  __byte_perm((unsigned)v2.x, (unsigned)v3.x, 0x0040),
                                  0x5410);
        unsigned tb = __byte_perm(__byte_perm((unsigned)v0.y, (unsigned)v1.y, 0x0040),
                                  __byte_perm((unsigned)v2.y, (unsigned)v3.y, 0x0040),
                                  0x5410);
        mxa = __vmaxs4(mxa, ta);
        mxb = __vmaxs4(mxb, tb);
        qa[g] = ta;
        qb[g] = tb;
    }
    int ma = (int)(signed char)(mxa & 0xFF);
    ma = max(ma, (int)(signed char)((mxa >> 8) & 0xFF));
    ma = max(ma, (int)(signed char)((mxa >> 16) & 0xFF));
    ma = max(ma, (int)(signed char)(mxa >> 24));
    int mb = (int)(signed char)(mxb & 0xFF);
    mb = max(mb, (int)(signed char)((mxb >> 8) & 0xFF));
    mb = max(mb, (int)(signed char)((mxb >> 16) & 0xFF));
    mb = max(mb, (int)(signed char)(mxb >> 24));
    *(int2*)&smax[cs * 64 + 2 * p] = make_int2(ma, mb);

    // ---- LUT build (overlaps outstanding loads of other warps) ----
    float ds = __ldg(ds_ptr);
    slut_i[tid] = (unsigned)(int)exp_lut_entry(tid, ds);
    slut_i[tid + 128] = (unsigned)(int)exp_lut_entry(tid + 128, ds);
    __syncthreads();                  // covers smax + slut_i

    // ---- cross-slice max for both pixels ----
    {
        int2 s0 = *(const int2*)&smax[0 * 64 + 2 * p];
        int2 s1 = *(const int2*)&smax[1 * 64 + 2 * p];
        int2 s2 = *(const int2*)&smax[2 * 64 + 2 * p];
        int2 s3 = *(const int2*)&smax[3 * 64 + 2 * p];
        ma = max(max(s0.x, s1.x), max(s2.x, s3.x));
        mb = max(max(s0.y, s1.y), max(s2.y, s3.y));
    }
    unsigned m4a = (unsigned)(ma & 0xFF) * 0x01010101u;
    unsigned m4b = (unsigned)(mb & 0xFF) * 0x01010101u;

    // ---- pass 2: d via VSUB4, integer LUT, integer sums; stage u16x2/pair ----
    int sa = 0, sb = 0;
#pragma unroll
    for (int g = 0; g < 8; g++) {
        unsigned d4a = __vsub4(m4a, qa[g]);          // per-byte (m-q) mod 256 = d
        unsigned d4b = __vsub4(m4b, qb[g]);
        unsigned ea0 = slut_i[(int)__byte_perm(d4a, 0, 0x4440)];
        unsigned ea1 = slut_i[(int)__byte_perm(d4a, 0, 0x4441)];
        unsigned ea2 = slut_i[(int)__byte_perm(d4a, 0, 0x4442)];
        unsigned ea3 = slut_i[(int)__byte_perm(d4a, 0, 0x4443)];
        unsigned eb0 = slut_i[(int)__byte_perm(d4b, 0, 0x4440)];
        unsigned eb1 = slut_i[(int)__byte_perm(d4b, 0, 0x4441)];
        unsigned eb2 = slut_i[(int)__byte_perm(d4b, 0, 0x4442)];
        unsigned eb3 = slut_i[(int)__byte_perm(d4b, 0, 0x4443)];
        sa += (int)((ea0 + ea1) + (ea2 + ea3));      // total < 2^22: exact
        sb += (int)((eb0 + eb1) + (eb2 + eb3));
        int c0 = cs * 32 + 4 * g;
        buf16[(c0 + 0) * 32 + p] = __byte_perm(ea0, eb0, 0x5410);  // a.lo16|b.lo16<<16
        buf16[(c0 + 1) * 32 + p] = __byte_perm(ea1, eb1, 0x5410);
        buf16[(c0 + 2) * 32 + p] = __byte_perm(ea2, eb2, 0x5410);
        buf16[(c0 + 3) * 32 + p] = __byte_perm(ea3, eb3, 0x5410);
    }
    *(int2*)&ssum[cs * 64 + 2 * p] = make_int2(sa, sb);
    __syncthreads();

    // ---- reciprocal: one thread per pixel (tid < 64) ----
    if (tid < PX) {
        int px = tid;
        float sum = (float)(((ssum[px] + ssum[64 + px]) +
                             (ssum[128 + px] + ssum[192 + px])));  // exact I2F
        // shift = ceil(log2(128)) = 7
        float sum_sh = rintf(sum * 0.0078125f);                 // exact /128
        sum_sh = fminf(fmaxf(sum_sh, -32768.0f), 32767.0f);
        const float DIVSC = (float)(2.0 / 65535.0 * 128.0);
        float v = __fmul_rn(sum_sh, DIVSC);
        const float RSCALE = (float)((1.0 / 0.1) * 2.0 / 65535.0);

        float r = quant_i16(__fdiv_rn(1.0f, 0.001f), RSCALE);   // left const
        if (v >= 0.001f) {                                      // line (0.001,0.1)
            float y0 = __fdiv_rn(1.0f, 0.001f), y1 = __fdiv_rn(1.0f, 0.1f);
            float t = __fadd_rn(y0, __fmul_rn(__fadd_rn(v, -0.001f),
                                              __fdiv_rn(__fadd_rn(y1, -y0), (float)(0.1 - 0.001))));
            r = quant_i16(t, RSCALE);
        }
        if (v >= 0.1f) {                                        // table (0.1,250)
            float idxf = rintf(__fmul_rn(__fadd_rn(v, -0.1f), (float)(255.0 / 249.9)));
            idxf = fminf(fmaxf(idxf, 0.0f), 255.0f);
            float step1 = __fdiv_rn((float)(250.0 - 0.1), 255.0f);
            float xs = __fadd_rn(0.1f, __fmul_rn(idxf, step1));
            r = quant_i16(__fdiv_rn(1.0f, xs), RSCALE);
        }
        if (v >= 250.0f) {                                      // table (250,500)
            float idxf = rintf(__fmul_rn(__fadd_rn(v, -250.0f), (float)(255.0 / 250.0)));
            idxf = fminf(fmaxf(idxf, 0.0f), 255.0f);
            float step2 = __fdiv_rn(250.0f, 255.0f);
            float xs = __fadd_rn(250.0f, __fmul_rn(idxf, step2));
            r = quant_i16(__fdiv_rn(1.0f, xs), RSCALE);
        }
        if (v >= 500.0f) {                                      // line (500,700)
            float y0 = __fdiv_rn(1.0f, 500.0f), y1 = __fdiv_rn(1.0f, 700.0f);
            float t = __fadd_rn(y0, __fmul_rn(__fadd_rn(v, -500.0f),
                                              __fdiv_rn(__fadd_rn(y1, -y0), 200.0f)));
            r = quant_i16(t, RSCALE);
        }
        if (v > 700.0f) r = quant_i16(__fdiv_rn(1.0f, 700.0f), RSCALE);
        srec[px] = r;
    }
    __syncthreads();

    // ---- pass 3: out = clip(round((exp_q*recip_q)*K), i8) * OUT_SCALE ----
    const float KF = (float)((2.0 / 65535.0) * ((1.0 / 0.1) * 2.0 / 65535.0) / (2.0 / 255.0));
    const float OUTSC = (float)(2.0 / 255.0);
    float r0 = srec[2 * p];
    float r1 = srec[2 * p + 1];
    float* po = out + (size_t)b * C_DIM * HW_DIM
                    + (size_t)(cs * 32) * HW_DIM + tilehw + 2 * p;
#pragma unroll
    for (int j = 0; j < 32; j++) {
        unsigned wv = buf16[(cs * 32 + j) * 32 + p];
        float ea = (float)(int)__byte_perm(wv, 0, 0x4410);   // lo16
        float eb = (float)(wv >> 16);                        // hi16
        float pa = rintf(__fmul_rn(__fmul_rn(ea, r0), KF));
        float pb = rintf(__fmul_rn(__fmul_rn(eb, r1), KF));
        pa = fminf(fmaxf(pa, -128.0f), 127.0f) * OUTSC;
        pb = fminf(fmaxf(pb, -128.0f), 127.0f) * OUTSC;
        __stcs((float2*)&po[j * HW_DIM], make_float2(pa, pb));
    }
}

extern "C" void kernel_launch(void* const* d_in, const int* in_sizes, int n_in,
                              void* d_out, int out_size) {
    const int* data = (const int*)d_in[0];
    const float* data_scale = (const float*)d_in[1];
    float* out = (float*)d_out;

    int total = in_sizes[0];
    int B = total / (C_DIM * HW_DIM);
    int blocks = B * (HW_DIM / PX);
    quant_softmax_kernel<<<blocks, NTHREADS>>>(data, out, data_scale);
}